// round 3
// baseline (speedup 1.0000x reference)
#include <cuda_runtime.h>
#include <cstdint>

// Problem constants
#define T_STEPS 512
#define HDIM    128
#define G4      512     // 4*H
#define OUTD    64
#define BSEL    255     // only batch row that affects the output
#define HPAD    68      // 64 + 4 pad floats per half (bank-conflict avoidance)
#define HBUF    136     // one h buffer = 2 halves * HPAD

// ---------------- scratch (no allocations allowed) ----------------
__device__ float g_xg[T_STEPS * G4];     // precomputed input gates for batch 255
__device__ float g_hout[256 * HDIM];     // h[255, 256+j, :]
__device__ float g_Wc[OUTD * HDIM];      // W2 @ W1
__device__ float g_bc[OUTD];             // W2 @ b1 + b2

// ---------------- helpers ----------------
__device__ __forceinline__ float fast_sigmoid(float x) {
    return 1.0f / (1.0f + __expf(-x));
}
__device__ __forceinline__ float fast_tanh(float x) {
    return 1.0f - 2.0f / (__expf(2.0f * x) + 1.0f);
}
__device__ __forceinline__ void fma_f32x2(unsigned long long& acc,
                                          unsigned long long a,
                                          unsigned long long b) {
    asm("fma.rn.f32x2 %0, %1, %2, %0;" : "+l"(acc) : "l"(a), "l"(b));
}
__device__ __forceinline__ unsigned long long add_f32x2(unsigned long long a,
                                                        unsigned long long b) {
    unsigned long long r;
    asm("add.rn.f32x2 %0, %1, %2;" : "=l"(r) : "l"(a), "l"(b));
    return r;
}
__device__ __forceinline__ uint32_t smem_u32(const void* p) {
    uint32_t a;
    asm("{ .reg .u64 t; cvta.to.shared.u64 t, %1; cvt.u32.u64 %0, t; }"
        : "=r"(a) : "l"(p));
    return a;
}
#define CLUSTER_SYNC() do { \
    asm volatile("barrier.cluster.arrive.aligned;" ::: "memory"); \
    asm volatile("barrier.cluster.wait.aligned;"   ::: "memory"); \
} while (0)

__device__ __forceinline__ void mbar_init(uint32_t mbar, uint32_t count) {
    asm volatile("mbarrier.init.shared.b64 [%0], %1;" :: "r"(mbar), "r"(count) : "memory");
}
__device__ __forceinline__ void mbar_arrive_local(uint32_t mbar) {
    asm volatile("mbarrier.arrive.release.cluster.shared::cta.b64 _, [%0];"
                 :: "r"(mbar) : "memory");
}
__device__ __forceinline__ void mbar_arrive_remote(uint32_t mbar) {
    asm volatile("mbarrier.arrive.release.cluster.shared::cluster.b64 _, [%0];"
                 :: "r"(mbar) : "memory");
}
__device__ __forceinline__ void mbar_wait_parity_cluster(uint32_t mbar, uint32_t parity) {
    asm volatile(
        "{\n\t"
        ".reg .pred P;\n"
        "WL%=:\n\t"
        "mbarrier.try_wait.parity.acquire.cluster.shared::cta.b64 P, [%0], %1;\n\t"
        "@P bra.uni WD%=;\n\t"
        "bra.uni WL%=;\n"
        "WD%=:\n\t"
        "}"
        :: "r"(mbar), "r"(parity) : "memory");
}

// ---------------- kernel 1: xg[t, j] = W_ih[j,:] . x[255,t,:] + b_ih[j] + b_hh[j]
__global__ void __launch_bounds__(512) xg_kernel(
    const float* __restrict__ x, const float* __restrict__ Wih,
    const float* __restrict__ bih, const float* __restrict__ bhh)
{
    __shared__ __align__(16) float xs[8][HDIM];
    int t0 = blockIdx.x * 8;
    int j  = threadIdx.x;

    for (int i = j; i < 8 * HDIM; i += 512) {
        int tt = i >> 7, d = i & 127;
        xs[tt][d] = x[((size_t)BSEL * T_STEPS + t0 + tt) * HDIM + d];
    }
    __syncthreads();

    const float4* wr4 = reinterpret_cast<const float4*>(Wih + j * HDIM);
    float acc[8];
    #pragma unroll
    for (int tt = 0; tt < 8; tt++) acc[tt] = 0.0f;

    #pragma unroll
    for (int q = 0; q < HDIM / 4; q++) {
        float4 w = wr4[q];
        #pragma unroll
        for (int tt = 0; tt < 8; tt++) {
            float4 xv = reinterpret_cast<const float4*>(xs[tt])[q];
            acc[tt] += w.x * xv.x + w.y * xv.y + w.z * xv.z + w.w * xv.w;
        }
    }
    float bb = bih[j] + bhh[j];
    #pragma unroll
    for (int tt = 0; tt < 8; tt++)
        g_xg[(t0 + tt) * G4 + j] = acc[tt] + bb;
}

// ---------------- kernel 2: collapse the two affine layers
__global__ void __launch_bounds__(512) mlp_precomp_kernel(
    const float* __restrict__ W1, const float* __restrict__ b1,
    const float* __restrict__ W2, const float* __restrict__ b2)
{
    int idx = blockIdx.x * blockDim.x + threadIdx.x;
    if (idx < OUTD * HDIM) {
        int o = idx >> 7, hh = idx & 127;
        float acc = 0.0f;
        #pragma unroll 4
        for (int m = 0; m < HDIM; m++)
            acc += W2[o * HDIM + m] * W1[m * HDIM + hh];
        g_Wc[idx] = acc;
    }
    if (idx < OUTD) {
        float acc = b2[idx];
        #pragma unroll 4
        for (int m = 0; m < HDIM; m++)
            acc += W2[idx * HDIM + m] * b1[m];
        g_bc[idx] = acc;
    }
}

// ---------------- kernel 3: sequential LSTM scan (batch 255 only)
// 2-CTA cluster, 512 threads each. Thread mapping: for tid,
//   half   = tid & 1          (which 64-wide half of h this thread's dot covers)
//   gate   = (tid >> 1) & 3   (i, f, g, o)
//   eLocal = tid >> 3         (element within this CTA's 64)
// => the 8 lanes {4 gates x 2 halves} of one element are CONSECUTIVE lanes of
// one warp: butterfly + shfl.idx replaces the smem gate exchange + barrier.
// Per-step sync: double-buffered h + one mbarrier (64 local + 64 remote arrivals).
__global__ void __cluster_dims__(2, 1, 1) __launch_bounds__(512, 1)
lstm_scan_kernel(const float* __restrict__ Whh)
{
    __shared__ __align__(16) float h_smem[2 * HBUF];
    __shared__ __align__(8) unsigned long long bar_storage;

    int tid = threadIdx.x;
    unsigned rank;
    asm("mov.u32 %0, %%cluster_ctarank;" : "=r"(rank));

    int half   = tid & 1;
    int gate   = (tid >> 1) & 3;
    int eLocal = tid >> 3;
    int ee     = (int)rank * 64 + eLocal;      // global hidden element
    int grow   = gate * HDIM + ee;             // row of W_hh / xg

    // register-resident weights: 32 packed f32x2 = 64 floats (this row-half)
    unsigned long long w2[32];
    {
        const unsigned long long* wsrc =
            reinterpret_cast<const unsigned long long*>(Whh + grow * HDIM + half * 64);
        #pragma unroll
        for (int q = 0; q < 32; q++) w2[q] = wsrc[q];
    }

    uint32_t lbar = smem_u32(&bar_storage);
    uint32_t rbar;
    asm("mapa.shared::cluster.u32 %0, %1, %2;" : "=r"(rbar) : "r"(lbar), "r"(rank ^ 1u));
    uint32_t hbase = smem_u32(h_smem);
    uint32_t rhbase;
    asm("mapa.shared::cluster.u32 %0, %1, %2;" : "=r"(rhbase) : "r"(hbase), "r"(rank ^ 1u));

    if (tid == 0) mbar_init(lbar, 128);
    // zero buffer 0 (input of step 0)
    if (tid < HBUF) h_smem[tid] = 0.0f;
    __syncthreads();
    CLUSTER_SYNC();   // both CTAs' mbarriers initialized + h zeroed

    bool writer = ((tid & 7) == 0);
    int  widx   = (ee < 64) ? ee : ee + 4;     // padded position in an h buffer
    int  lane   = tid & 31;
    int  gbase  = lane & ~7;                   // first lane of this element's group

    float c = 0.0f;                            // cell state (only writer's copy used)
    const float* xg_row = g_xg + grow;

    for (int t = 0; t < T_STEPS; t++) {
        // xg prefetch (L2) — independent of h, overlaps the matvec
        float xgv = __ldg(xg_row + t * G4);

        // half-row matvec: 32 packed FMAs over this step's h buffer
        const ulonglong2* hp2 = reinterpret_cast<const ulonglong2*>(
            h_smem + (t & 1) * HBUF + half * HPAD);
        unsigned long long a0 = 0ull, a1 = 0ull, a2 = 0ull, a3 = 0ull;
        #pragma unroll
        for (int q = 0; q < 16; q += 2) {
            ulonglong2 h0 = hp2[q];
            ulonglong2 h1 = hp2[q + 1];
            fma_f32x2(a0, w2[2 * q + 0], h0.x);
            fma_f32x2(a1, w2[2 * q + 1], h0.y);
            fma_f32x2(a2, w2[2 * q + 2], h1.x);
            fma_f32x2(a3, w2[2 * q + 3], h1.y);
        }
        unsigned long long s = add_f32x2(add_f32x2(a0, a1), add_f32x2(a2, a3));
        float sx, sy;
        asm("mov.b64 {%0,%1}, %2;" : "=f"(sx), "=f"(sy) : "l"(s));
        float acc = sx + sy;

        // combine halves (lanes l, l^1), then row dot is complete
        float full = acc + __shfl_xor_sync(0xFFFFFFFFu, acc, 1) + xgv;

        // gather the 4 gate dots of this element from the 8-lane group
        float gi = __shfl_sync(0xFFFFFFFFu, full, gbase + 0);
        float gf = __shfl_sync(0xFFFFFFFFu, full, gbase + 2);
        float gg = __shfl_sync(0xFFFFFFFFu, full, gbase + 4);
        float go = __shfl_sync(0xFFFFFFFFu, full, gbase + 6);

        if (writer) {
            float iv = fast_sigmoid(gi);
            float fv = fast_sigmoid(gf);
            float gv = fast_tanh(gg);
            float ov = fast_sigmoid(go);
            c = fv * c + iv * gv;
            float h = ov * fast_tanh(c);

            // write h into NEXT step's buffer, locally and in the peer CTA
            uint32_t off = ((t + 1) & 1) * (HBUF * 4) + widx * 4;
            asm volatile("st.shared.f32 [%0], %1;"
                         :: "r"(hbase + off), "f"(h) : "memory");
            asm volatile("st.shared::cluster.f32 [%0], %1;"
                         :: "r"(rhbase + off), "f"(h) : "memory");
            mbar_arrive_local(lbar);
            mbar_arrive_remote(rbar);

            if (t >= 256) g_hout[(t - 256) * HDIM + ee] = h;
        }
        // wait: 64 local + 64 remote arrivals => next h buffer complete
        mbar_wait_parity_cluster(lbar, (uint32_t)(t & 1));
    }
    CLUSTER_SYNC();
}

// ---------------- kernel 4: out[j, o] = bc[o] + Wc[o,:] . h[255, 256+j, :]
__global__ void __launch_bounds__(64) mlp_final_kernel(float* __restrict__ out)
{
    __shared__ __align__(16) float hs[HDIM];
    int j = blockIdx.x;
    int o = threadIdx.x;
    hs[o]      = g_hout[j * HDIM + o];
    hs[o + 64] = g_hout[j * HDIM + 64 + o];
    __syncthreads();

    const float4* wr4 = reinterpret_cast<const float4*>(g_Wc + o * HDIM);
    float a0 = 0.0f, a1 = 0.0f;
    #pragma unroll
    for (int q = 0; q < HDIM / 4; q += 2) {
        float4 w0 = wr4[q],     x0 = reinterpret_cast<const float4*>(hs)[q];
        float4 w1 = wr4[q + 1], x1 = reinterpret_cast<const float4*>(hs)[q + 1];
        a0 += w0.x * x0.x + w0.y * x0.y + w0.z * x0.z + w0.w * x0.w;
        a1 += w1.x * x1.x + w1.y * x1.y + w1.z * x1.z + w1.w * x1.w;
    }
    out[j * OUTD + o] = g_bc[o] + a0 + a1;
}

// ---------------- launch ----------------
extern "C" void kernel_launch(void* const* d_in, const int* in_sizes, int n_in,
                              void* d_out, int out_size)
{
    const float* x   = (const float*)d_in[0];
    const float* Wih = (const float*)d_in[1];
    const float* Whh = (const float*)d_in[2];
    const float* bih = (const float*)d_in[3];
    const float* bhh = (const float*)d_in[4];
    const float* W1  = (const float*)d_in[5];
    const float* b1  = (const float*)d_in[6];
    const float* W2  = (const float*)d_in[7];
    const float* b2  = (const float*)d_in[8];
    float* out = (float*)d_out;

    xg_kernel<<<64, 512>>>(x, Wih, bih, bhh);
    mlp_precomp_kernel<<<16, 512>>>(W1, b1, W2, b2);
    lstm_scan_kernel<<<2, 512>>>(Whh);
    mlp_final_kernel<<<256, 64>>>(out);
}

// round 4
// speedup vs baseline: 1.0003x; 1.0003x over previous
#include <cuda_runtime.h>
#include <cstdint>

// Problem constants
#define T_STEPS 512
#define HDIM    128
#define G4      512     // 4*H
#define OUTD    64
#define BSEL    255     // only batch row that affects the output
#define HPAD    68      // 64 + 4 pad floats per half (bank-conflict avoidance)
#define HBUF    136     // one h buffer = 2 halves * HPAD

// ---------------- scratch (no allocations allowed) ----------------
__device__ float g_xg[T_STEPS * G4];     // precomputed input gates for batch 255
__device__ float g_hout[256 * HDIM];     // h[255, 256+j, :]
__device__ float g_Wc[OUTD * HDIM];      // W2 @ W1
__device__ float g_bc[OUTD];             // W2 @ b1 + b2

// ---------------- helpers ----------------
__device__ __forceinline__ float fast_sigmoid(float x) {
    return 1.0f / (1.0f + __expf(-x));
}
__device__ __forceinline__ float fast_tanh(float x) {
    return 1.0f - 2.0f / (__expf(2.0f * x) + 1.0f);
}
__device__ __forceinline__ void fma_f32x2(unsigned long long& acc,
                                          unsigned long long a,
                                          unsigned long long b) {
    asm("fma.rn.f32x2 %0, %1, %2, %0;" : "+l"(acc) : "l"(a), "l"(b));
}
__device__ __forceinline__ unsigned long long add_f32x2(unsigned long long a,
                                                        unsigned long long b) {
    unsigned long long r;
    asm("add.rn.f32x2 %0, %1, %2;" : "=l"(r) : "l"(a), "l"(b));
    return r;
}
__device__ __forceinline__ uint32_t smem_u32(const void* p) {
    uint32_t a;
    asm("{ .reg .u64 t; cvta.to.shared.u64 t, %1; cvt.u32.u64 %0, t; }"
        : "=r"(a) : "l"(p));
    return a;
}
#define CLUSTER_SYNC() do { \
    asm volatile("barrier.cluster.arrive.aligned;" ::: "memory"); \
    asm volatile("barrier.cluster.wait.aligned;"   ::: "memory"); \
} while (0)

__device__ __forceinline__ void mbar_init(uint32_t mbar, uint32_t count) {
    asm volatile("mbarrier.init.shared.b64 [%0], %1;" :: "r"(mbar), "r"(count) : "memory");
}
__device__ __forceinline__ void mbar_arrive_local(uint32_t mbar) {
    asm volatile("mbarrier.arrive.release.cluster.shared::cta.b64 _, [%0];"
                 :: "r"(mbar) : "memory");
}
__device__ __forceinline__ void mbar_arrive_remote(uint32_t mbar) {
    asm volatile("mbarrier.arrive.release.cluster.shared::cluster.b64 _, [%0];"
                 :: "r"(mbar) : "memory");
}
__device__ __forceinline__ void mbar_wait_parity_cluster(uint32_t mbar, uint32_t parity) {
    asm volatile(
        "{\n\t"
        ".reg .pred P;\n"
        "WL%=:\n\t"
        "mbarrier.try_wait.parity.acquire.cluster.shared::cta.b64 P, [%0], %1;\n\t"
        "@P bra.uni WD%=;\n\t"
        "bra.uni WL%=;\n"
        "WD%=:\n\t"
        "}"
        :: "r"(mbar), "r"(parity) : "memory");
}

// ---------------- kernel 1: xg[t, j] = W_ih[j,:] . x[255,t,:] + b_ih[j] + b_hh[j]
__global__ void __launch_bounds__(512) xg_kernel(
    const float* __restrict__ x, const float* __restrict__ Wih,
    const float* __restrict__ bih, const float* __restrict__ bhh)
{
    __shared__ __align__(16) float xs[8][HDIM];
    int t0 = blockIdx.x * 8;
    int j  = threadIdx.x;

    for (int i = j; i < 8 * HDIM; i += 512) {
        int tt = i >> 7, d = i & 127;
        xs[tt][d] = x[((size_t)BSEL * T_STEPS + t0 + tt) * HDIM + d];
    }
    __syncthreads();

    const float4* wr4 = reinterpret_cast<const float4*>(Wih + j * HDIM);
    float acc[8];
    #pragma unroll
    for (int tt = 0; tt < 8; tt++) acc[tt] = 0.0f;

    #pragma unroll
    for (int q = 0; q < HDIM / 4; q++) {
        float4 w = wr4[q];
        #pragma unroll
        for (int tt = 0; tt < 8; tt++) {
            float4 xv = reinterpret_cast<const float4*>(xs[tt])[q];
            acc[tt] += w.x * xv.x + w.y * xv.y + w.z * xv.z + w.w * xv.w;
        }
    }
    float bb = bih[j] + bhh[j];
    #pragma unroll
    for (int tt = 0; tt < 8; tt++)
        g_xg[(t0 + tt) * G4 + j] = acc[tt] + bb;
}

// ---------------- kernel 2: collapse the two affine layers
__global__ void __launch_bounds__(512) mlp_precomp_kernel(
    const float* __restrict__ W1, const float* __restrict__ b1,
    const float* __restrict__ W2, const float* __restrict__ b2)
{
    int idx = blockIdx.x * blockDim.x + threadIdx.x;
    if (idx < OUTD * HDIM) {
        int o = idx >> 7, hh = idx & 127;
        float acc = 0.0f;
        #pragma unroll 4
        for (int m = 0; m < HDIM; m++)
            acc += W2[o * HDIM + m] * W1[m * HDIM + hh];
        g_Wc[idx] = acc;
    }
    if (idx < OUTD) {
        float acc = b2[idx];
        #pragma unroll 4
        for (int m = 0; m < HDIM; m++)
            acc += W2[idx * HDIM + m] * b1[m];
        g_bc[idx] = acc;
    }
}

// ---------------- kernel 3: sequential LSTM scan (batch 255 only)
// 2-CTA cluster, 512 threads each. Thread mapping: for tid,
//   half   = tid & 1          (which 64-wide half of h this thread's dot covers)
//   gate   = (tid >> 1) & 3   (i, f, g, o)
//   eLocal = tid >> 3         (element within this CTA's 64)
// => the 8 lanes {4 gates x 2 halves} of one element are CONSECUTIVE lanes of
// one warp: butterfly + shfl.idx replaces the smem gate exchange + barrier.
// Per-step sync: double-buffered h + one mbarrier (64 local + 64 remote arrivals).
__global__ void __cluster_dims__(2, 1, 1) __launch_bounds__(512, 1)
lstm_scan_kernel(const float* __restrict__ Whh)
{
    __shared__ __align__(16) float h_smem[2 * HBUF];
    __shared__ __align__(8) unsigned long long bar_storage;

    int tid = threadIdx.x;
    unsigned rank;
    asm("mov.u32 %0, %%cluster_ctarank;" : "=r"(rank));

    int half   = tid & 1;
    int gate   = (tid >> 1) & 3;
    int eLocal = tid >> 3;
    int ee     = (int)rank * 64 + eLocal;      // global hidden element
    int grow   = gate * HDIM + ee;             // row of W_hh / xg

    // register-resident weights: 32 packed f32x2 = 64 floats (this row-half)
    unsigned long long w2[32];
    {
        const unsigned long long* wsrc =
            reinterpret_cast<const unsigned long long*>(Whh + grow * HDIM + half * 64);
        #pragma unroll
        for (int q = 0; q < 32; q++) w2[q] = wsrc[q];
    }

    uint32_t lbar = smem_u32(&bar_storage);
    uint32_t rbar;
    asm("mapa.shared::cluster.u32 %0, %1, %2;" : "=r"(rbar) : "r"(lbar), "r"(rank ^ 1u));
    uint32_t hbase = smem_u32(h_smem);
    uint32_t rhbase;
    asm("mapa.shared::cluster.u32 %0, %1, %2;" : "=r"(rhbase) : "r"(hbase), "r"(rank ^ 1u));

    if (tid == 0) mbar_init(lbar, 128);
    // zero buffer 0 (input of step 0)
    if (tid < HBUF) h_smem[tid] = 0.0f;
    __syncthreads();
    CLUSTER_SYNC();   // both CTAs' mbarriers initialized + h zeroed

    bool writer = ((tid & 7) == 0);
    int  widx   = (ee < 64) ? ee : ee + 4;     // padded position in an h buffer
    int  lane   = tid & 31;
    int  gbase  = lane & ~7;                   // first lane of this element's group

    float c = 0.0f;                            // cell state (only writer's copy used)
    const float* xg_row = g_xg + grow;

    for (int t = 0; t < T_STEPS; t++) {
        // xg prefetch (L2) — independent of h, overlaps the matvec
        float xgv = __ldg(xg_row + t * G4);

        // half-row matvec: 32 packed FMAs over this step's h buffer
        const ulonglong2* hp2 = reinterpret_cast<const ulonglong2*>(
            h_smem + (t & 1) * HBUF + half * HPAD);
        unsigned long long a0 = 0ull, a1 = 0ull, a2 = 0ull, a3 = 0ull;
        #pragma unroll
        for (int q = 0; q < 16; q += 2) {
            ulonglong2 h0 = hp2[q];
            ulonglong2 h1 = hp2[q + 1];
            fma_f32x2(a0, w2[2 * q + 0], h0.x);
            fma_f32x2(a1, w2[2 * q + 1], h0.y);
            fma_f32x2(a2, w2[2 * q + 2], h1.x);
            fma_f32x2(a3, w2[2 * q + 3], h1.y);
        }
        unsigned long long s = add_f32x2(add_f32x2(a0, a1), add_f32x2(a2, a3));
        float sx, sy;
        asm("mov.b64 {%0,%1}, %2;" : "=f"(sx), "=f"(sy) : "l"(s));
        float acc = sx + sy;

        // combine halves (lanes l, l^1), then row dot is complete
        float full = acc + __shfl_xor_sync(0xFFFFFFFFu, acc, 1) + xgv;

        // gather the 4 gate dots of this element from the 8-lane group
        float gi = __shfl_sync(0xFFFFFFFFu, full, gbase + 0);
        float gf = __shfl_sync(0xFFFFFFFFu, full, gbase + 2);
        float gg = __shfl_sync(0xFFFFFFFFu, full, gbase + 4);
        float go = __shfl_sync(0xFFFFFFFFu, full, gbase + 6);

        if (writer) {
            float iv = fast_sigmoid(gi);
            float fv = fast_sigmoid(gf);
            float gv = fast_tanh(gg);
            float ov = fast_sigmoid(go);
            c = fv * c + iv * gv;
            float h = ov * fast_tanh(c);

            // write h into NEXT step's buffer, locally and in the peer CTA
            uint32_t off = ((t + 1) & 1) * (HBUF * 4) + widx * 4;
            asm volatile("st.shared.f32 [%0], %1;"
                         :: "r"(hbase + off), "f"(h) : "memory");
            asm volatile("st.shared::cluster.f32 [%0], %1;"
                         :: "r"(rhbase + off), "f"(h) : "memory");
            mbar_arrive_local(lbar);
            mbar_arrive_remote(rbar);

            if (t >= 256) g_hout[(t - 256) * HDIM + ee] = h;
        }
        // wait: 64 local + 64 remote arrivals => next h buffer complete
        mbar_wait_parity_cluster(lbar, (uint32_t)(t & 1));
    }
    CLUSTER_SYNC();
}

// ---------------- kernel 4: out[j, o] = bc[o] + Wc[o,:] . h[255, 256+j, :]
__global__ void __launch_bounds__(64) mlp_final_kernel(float* __restrict__ out)
{
    __shared__ __align__(16) float hs[HDIM];
    int j = blockIdx.x;
    int o = threadIdx.x;
    hs[o]      = g_hout[j * HDIM + o];
    hs[o + 64] = g_hout[j * HDIM + 64 + o];
    __syncthreads();

    const float4* wr4 = reinterpret_cast<const float4*>(g_Wc + o * HDIM);
    float a0 = 0.0f, a1 = 0.0f;
    #pragma unroll
    for (int q = 0; q < HDIM / 4; q += 2) {
        float4 w0 = wr4[q],     x0 = reinterpret_cast<const float4*>(hs)[q];
        float4 w1 = wr4[q + 1], x1 = reinterpret_cast<const float4*>(hs)[q + 1];
        a0 += w0.x * x0.x + w0.y * x0.y + w0.z * x0.z + w0.w * x0.w;
        a1 += w1.x * x1.x + w1.y * x1.y + w1.z * x1.z + w1.w * x1.w;
    }
    out[j * OUTD + o] = g_bc[o] + a0 + a1;
}

// ---------------- launch ----------------
extern "C" void kernel_launch(void* const* d_in, const int* in_sizes, int n_in,
                              void* d_out, int out_size)
{
    const float* x   = (const float*)d_in[0];
    const float* Wih = (const float*)d_in[1];
    const float* Whh = (const float*)d_in[2];
    const float* bih = (const float*)d_in[3];
    const float* bhh = (const float*)d_in[4];
    const float* W1  = (const float*)d_in[5];
    const float* b1  = (const float*)d_in[6];
    const float* W2  = (const float*)d_in[7];
    const float* b2  = (const float*)d_in[8];
    float* out = (float*)d_out;

    xg_kernel<<<64, 512>>>(x, Wih, bih, bhh);
    mlp_precomp_kernel<<<16, 512>>>(W1, b1, W2, b2);
    lstm_scan_kernel<<<2, 512>>>(Whh);
    mlp_final_kernel<<<256, 64>>>(out);
}

// round 5
// speedup vs baseline: 1.2320x; 1.2317x over previous
#include <cuda_runtime.h>
#include <cstdint>

// Problem constants
#define T_STEPS 512
#define HDIM    128
#define G4      512     // 4*H
#define OUTD    64
#define BSEL    255     // only batch row that affects the output
#define SLICEF  36      // 32 floats + 4 pad per column-slice (bank shift)
#define HBUF    (4 * SLICEF)   // one h buffer = 144 floats

// ---------------- scratch (no allocations allowed) ----------------
__device__ float g_xg[T_STEPS * G4];     // precomputed input gates for batch 255
__device__ float g_hout[256 * HDIM];     // h[255, 256+j, :]
__device__ float g_Wc[OUTD * HDIM];      // W2 @ W1
__device__ float g_bc[OUTD];             // W2 @ b1 + b2

// ---------------- helpers ----------------
__device__ __forceinline__ float fast_sigmoid(float x) {
    return 1.0f / (1.0f + __expf(-x));
}
__device__ __forceinline__ float fast_tanh(float x) {
    return 1.0f - 2.0f / (__expf(2.0f * x) + 1.0f);
}
__device__ __forceinline__ void fma_f32x2(unsigned long long& acc,
                                          unsigned long long a,
                                          unsigned long long b) {
    asm("fma.rn.f32x2 %0, %1, %2, %0;" : "+l"(acc) : "l"(a), "l"(b));
}
__device__ __forceinline__ unsigned long long add_f32x2(unsigned long long a,
                                                        unsigned long long b) {
    unsigned long long r;
    asm("add.rn.f32x2 %0, %1, %2;" : "=l"(r) : "l"(a), "l"(b));
    return r;
}
__device__ __forceinline__ uint32_t smem_u32(const void* p) {
    uint32_t a;
    asm("{ .reg .u64 t; cvta.to.shared.u64 t, %1; cvt.u32.u64 %0, t; }"
        : "=r"(a) : "l"(p));
    return a;
}
#define CLUSTER_SYNC() do { \
    asm volatile("barrier.cluster.arrive.aligned;" ::: "memory"); \
    asm volatile("barrier.cluster.wait.aligned;"   ::: "memory"); \
} while (0)

// ---------------- kernel 1: xg[t, j] = W_ih[j,:] . x[255,t,:] + b_ih[j] + b_hh[j]
__global__ void __launch_bounds__(512) xg_kernel(
    const float* __restrict__ x, const float* __restrict__ Wih,
    const float* __restrict__ bih, const float* __restrict__ bhh)
{
    __shared__ __align__(16) float xs[8][HDIM];
    int t0 = blockIdx.x * 8;
    int j  = threadIdx.x;

    for (int i = j; i < 8 * HDIM; i += 512) {
        int tt = i >> 7, d = i & 127;
        xs[tt][d] = x[((size_t)BSEL * T_STEPS + t0 + tt) * HDIM + d];
    }
    __syncthreads();

    const float4* wr4 = reinterpret_cast<const float4*>(Wih + j * HDIM);
    float acc[8];
    #pragma unroll
    for (int tt = 0; tt < 8; tt++) acc[tt] = 0.0f;

    #pragma unroll
    for (int q = 0; q < HDIM / 4; q++) {
        float4 w = wr4[q];
        #pragma unroll
        for (int tt = 0; tt < 8; tt++) {
            float4 xv = reinterpret_cast<const float4*>(xs[tt])[q];
            acc[tt] += w.x * xv.x + w.y * xv.y + w.z * xv.z + w.w * xv.w;
        }
    }
    float bb = bih[j] + bhh[j];
    #pragma unroll
    for (int tt = 0; tt < 8; tt++)
        g_xg[(t0 + tt) * G4 + j] = acc[tt] + bb;
}

// ---------------- kernel 2: collapse the two affine layers
__global__ void __launch_bounds__(512) mlp_precomp_kernel(
    const float* __restrict__ W1, const float* __restrict__ b1,
    const float* __restrict__ W2, const float* __restrict__ b2)
{
    int idx = blockIdx.x * blockDim.x + threadIdx.x;
    if (idx < OUTD * HDIM) {
        int o = idx >> 7, hh = idx & 127;
        float acc = 0.0f;
        #pragma unroll 4
        for (int m = 0; m < HDIM; m++)
            acc += W2[o * HDIM + m] * W1[m * HDIM + hh];
        g_Wc[idx] = acc;
    }
    if (idx < OUTD) {
        float acc = b2[idx];
        #pragma unroll 4
        for (int m = 0; m < HDIM; m++)
            acc += W2[idx * HDIM + m] * b1[m];
        g_bc[idx] = acc;
    }
}

// ---------------- kernel 3: sequential LSTM scan (batch 255 only)
// 2-CTA cluster, 256 threads each. Thread tid:
//   q = tid & 3       -> 32-column slice [q*32, q*32+32) of h
//   eL = tid >> 2     -> element within this CTA's 64
// Each thread owns ALL 4 gate rows of its element over its slice:
//   128 weights in registers (64 u64), 32 h-floats loaded ONCE per step
//   (8 LDS.128) and reused across the 4 gates -> 4x less smem traffic and
//   4x fewer LDS than R1. Row sums completed by 2 shfl_xor butterflies in
//   the 4-lane group; xg folded in pre-reduction (lane q adds gate q's xg).
// Sync: double-buffered h + ONE barrier.cluster per step.
__global__ void __cluster_dims__(2, 1, 1) __launch_bounds__(256, 1)
lstm_scan_kernel(const float* __restrict__ Whh)
{
    __shared__ __align__(16) float h_smem[2 * HBUF];

    int tid = threadIdx.x;
    unsigned rank;
    asm("mov.u32 %0, %%cluster_ctarank;" : "=r"(rank));

    int q  = tid & 3;
    int eL = tid >> 2;
    int e  = (int)rank * 64 + eL;          // global hidden element

    // register-resident weights: w2[g][k] covers gate g, cols [q*32+2k, +2)
    unsigned long long w2[4][16];
    #pragma unroll
    for (int g = 0; g < 4; g++) {
        const unsigned long long* wsrc = reinterpret_cast<const unsigned long long*>(
            Whh + (size_t)(g * HDIM + e) * HDIM + q * 32);
        #pragma unroll
        for (int k = 0; k < 16; k++) w2[g][k] = wsrc[k];
    }

    uint32_t hbase = smem_u32(h_smem);
    uint32_t rhbase;
    asm("mapa.shared::cluster.u32 %0, %1, %2;" : "=r"(rhbase) : "r"(hbase), "r"(rank ^ 1u));

    // zero buffer 0 (input of step 0)
    if (tid < HBUF) h_smem[tid] = 0.0f;
    __syncthreads();
    CLUSTER_SYNC();

    bool writer = (q == 0);
    // writer's padded slot for element e in an h buffer (slice e>>5, pos e&31)
    uint32_t woff = (uint32_t)(((e >> 5) * SLICEF + (e & 31)) * 4);

    float c = 0.0f;                        // redundant across the 4 lanes (same value)
    const float* xg_base = g_xg + q * HDIM + e;   // row (gate q, element e)

    for (int t = 0; t < T_STEPS; t++) {
        // xg for gate q of element e (L2) — independent of h, overlaps matvec
        float xgv = __ldg(xg_base + t * G4);

        // load this thread's 32 h floats once (slice q of current buffer)
        const ulonglong2* hp2 = reinterpret_cast<const ulonglong2*>(
            h_smem + (t & 1) * HBUF + q * SLICEF);
        unsigned long long hreg[16];
        #pragma unroll
        for (int k = 0; k < 8; k++) {
            ulonglong2 v = hp2[k];
            hreg[2 * k] = v.x;
            hreg[2 * k + 1] = v.y;
        }

        // 4 gate partial dots over the 32-col slice (reusing hreg)
        float p[4];
        #pragma unroll
        for (int g = 0; g < 4; g++) {
            unsigned long long a0 = 0ull, a1 = 0ull;
            #pragma unroll
            for (int k = 0; k < 16; k += 2) {
                fma_f32x2(a0, w2[g][k],     hreg[k]);
                fma_f32x2(a1, w2[g][k + 1], hreg[k + 1]);
            }
            unsigned long long s = add_f32x2(a0, a1);
            float sx, sy;
            asm("mov.b64 {%0,%1}, %2;" : "=f"(sx), "=f"(sy) : "l"(s));
            p[g] = sx + sy;
        }
        p[q] += xgv;   // each gate's xg added exactly once across the group

        // butterfly-reduce the 4-lane group: all lanes end with full gate sums
        #pragma unroll
        for (int g = 0; g < 4; g++) p[g] += __shfl_xor_sync(0xFFFFFFFFu, p[g], 1);
        #pragma unroll
        for (int g = 0; g < 4; g++) p[g] += __shfl_xor_sync(0xFFFFFFFFu, p[g], 2);

        // gate math (redundant in all 4 lanes -> no divergence, same c everywhere)
        float iv = fast_sigmoid(p[0]);
        float fv = fast_sigmoid(p[1]);
        float gv = fast_tanh(p[2]);
        float ov = fast_sigmoid(p[3]);
        c = fv * c + iv * gv;
        float h = ov * fast_tanh(c);

        if (writer) {
            uint32_t off = ((t + 1) & 1) * (HBUF * 4) + woff;
            asm volatile("st.shared.f32 [%0], %1;"
                         :: "r"(hbase + off), "f"(h) : "memory");
            asm volatile("st.shared::cluster.f32 [%0], %1;"
                         :: "r"(rhbase + off), "f"(h) : "memory");
            if (t >= 256) g_hout[(t - 256) * HDIM + e] = h;
        }
        // one cluster barrier per step (release/acquire covers DSMEM stores)
        CLUSTER_SYNC();
    }
}

// ---------------- kernel 4: out[j, o] = bc[o] + Wc[o,:] . h[255, 256+j, :]
__global__ void __launch_bounds__(64) mlp_final_kernel(float* __restrict__ out)
{
    __shared__ __align__(16) float hs[HDIM];
    int j = blockIdx.x;
    int o = threadIdx.x;
    hs[o]      = g_hout[j * HDIM + o];
    hs[o + 64] = g_hout[j * HDIM + 64 + o];
    __syncthreads();

    const float4* wr4 = reinterpret_cast<const float4*>(g_Wc + o * HDIM);
    float a0 = 0.0f, a1 = 0.0f;
    #pragma unroll
    for (int qq = 0; qq < HDIM / 4; qq += 2) {
        float4 w0 = wr4[qq],     x0 = reinterpret_cast<const float4*>(hs)[qq];
        float4 w1 = wr4[qq + 1], x1 = reinterpret_cast<const float4*>(hs)[qq + 1];
        a0 += w0.x * x0.x + w0.y * x0.y + w0.z * x0.z + w0.w * x0.w;
        a1 += w1.x * x1.x + w1.y * x1.y + w1.z * x1.z + w1.w * x1.w;
    }
    out[j * OUTD + o] = g_bc[o] + a0 + a1;
}

// ---------------- launch ----------------
extern "C" void kernel_launch(void* const* d_in, const int* in_sizes, int n_in,
                              void* d_out, int out_size)
{
    const float* x   = (const float*)d_in[0];
    const float* Wih = (const float*)d_in[1];
    const float* Whh = (const float*)d_in[2];
    const float* bih = (const float*)d_in[3];
    const float* bhh = (const float*)d_in[4];
    const float* W1  = (const float*)d_in[5];
    const float* b1  = (const float*)d_in[6];
    const float* W2  = (const float*)d_in[7];
    const float* b2  = (const float*)d_in[8];
    float* out = (float*)d_out;

    xg_kernel<<<64, 512>>>(x, Wih, bih, bhh);
    mlp_precomp_kernel<<<16, 512>>>(W1, b1, W2, b2);
    lstm_scan_kernel<<<2, 256>>>(Whh);
    mlp_final_kernel<<<256, 64>>>(out);
}